// round 4
// baseline (speedup 1.0000x reference)
#include <cuda_runtime.h>
#include <math.h>

#define RES   160
#define R3    (RES*RES*RES)
#define NRAY  2048
#define NS    558
#define NPAIR 279
#define NEARC 0.05f
#define FARC  3.5f
#define BGC   1.0f
#define STEPW 0.00625f                 /* STEPSIZE * VOXEL = 0.5 * 0.0125 */
#define ACT_SHIFT -4.5951198501345898f /* log(1/(1-0.01)-1) */

typedef unsigned long long u64;

// ---- packed f32x2 helpers (Blackwell-only; ptxas never auto-fuses FFMA2) ----
__device__ __forceinline__ u64 pk2(float lo, float hi) {
    u64 r; asm("mov.b64 %0, {%1, %2};" : "=l"(r) : "f"(lo), "f"(hi)); return r;
}
__device__ __forceinline__ void upk2(u64 v, float& lo, float& hi) {
    asm("mov.b64 {%0, %1}, %2;" : "=f"(lo), "=f"(hi) : "l"(v));
}
__device__ __forceinline__ void fma2(u64& d, u64 a, u64 b) {
    asm("fma.rn.f32x2 %0, %1, %2, %0;" : "+l"(d) : "l"(a), "l"(b));
}

// ---- device scratch (static; no allocations allowed) ----
__device__ float g_grid_t[(size_t)R3 * 12];   // channel-last grid, 196.6 MB
__device__ float g_rayinfo[NRAY * 4];         // tmin, |d|, mask, pad
__device__ float g_dbias[NRAY * 16];          // per-ray dir-layer1 bias (emb folded)

// =====================================================================
// Kernel 0: transpose grid (C,R,R,R) -> (R,R,R,C) channel-last
// =====================================================================
__global__ void k_transpose(const float* __restrict__ g) {
    int v = blockIdx.x * blockDim.x + threadIdx.x;
    if (v >= R3) return;
    float a[12];
#pragma unroll
    for (int c = 0; c < 12; c++) a[c] = __ldg(g + (size_t)c * R3 + v);
    float4* dst = reinterpret_cast<float4*>(g_grid_t + (size_t)v * 12);
    dst[0] = make_float4(a[0], a[1], a[2], a[3]);
    dst[1] = make_float4(a[4], a[5], a[6], a[7]);
    dst[2] = make_float4(a[8], a[9], a[10], a[11]);
}

// =====================================================================
// Kernel 1: per-ray precompute (tmin, |d|, mask, dir-layer1 bias)
// =====================================================================
__global__ void k_raypre(const float* __restrict__ ro, const float* __restrict__ rd,
                         const float* __restrict__ vd, const float* __restrict__ dw1,
                         const float* __restrict__ db1) {
    int r = blockIdx.x * blockDim.x + threadIdx.x;
    if (r >= NRAY) return;
    float ox = ro[3*r], oy = ro[3*r+1], oz = ro[3*r+2];
    float dx = rd[3*r], dy = rd[3*r+1], dz = rd[3*r+2];
    float vx = (dx == 0.f) ? 1e-6f : dx;
    float vy = (dy == 0.f) ? 1e-6f : dy;
    float vz = (dz == 0.f) ? 1e-6f : dz;
    float rax = (1.f - ox) / vx, rbx = (-1.f - ox) / vx;
    float ray_ = (1.f - oy) / vy, rby = (-1.f - oy) / vy;
    float raz = (1.f - oz) / vz, rbz = (-1.f - oz) / vz;
    float tmn = fmaxf(fmaxf(fminf(rax, rbx), fminf(ray_, rby)), fminf(raz, rbz));
    float tmx = fminf(fminf(fmaxf(rax, rbx), fmaxf(ray_, rby)), fmaxf(raz, rbz));
    tmn = fminf(fmaxf(tmn, NEARC), FARC);
    tmx = fminf(fmaxf(tmx, NEARC), FARC);
    float mask = (tmx <= tmn) ? 1.f : 0.f;
    float nn = sqrtf(dx*dx + dy*dy + dz*dz);
    g_rayinfo[4*r+0] = tmn;
    g_rayinfo[4*r+1] = nn;
    g_rayinfo[4*r+2] = mask;
    g_rayinfo[4*r+3] = 0.f;

    float wx = vd[3*r], wy = vd[3*r+1], wz = vd[3*r+2];
    float emb[39];
    emb[0] = wx; emb[1] = wy; emb[2] = wz;
    float f = 1.f;
#pragma unroll
    for (int l = 0; l < 6; l++) {
        emb[3+6*l+0] = sinf(wx*f); emb[3+6*l+1] = sinf(wy*f); emb[3+6*l+2] = sinf(wz*f);
        emb[3+6*l+3] = cosf(wx*f); emb[3+6*l+4] = cosf(wy*f); emb[3+6*l+5] = cosf(wz*f);
        f *= 2.f;
    }
#pragma unroll
    for (int j = 0; j < 16; j++) {
        float acc = db1[j];
#pragma unroll
        for (int k = 0; k < 39; k++) acc += emb[k] * dw1[(15+k)*16 + j];
        g_dbias[16*r + j] = acc;
    }
}

// =====================================================================
// Kernel 2 (fused): per-sample MLPs + per-ray compositing. Block == ray.
// Threads handle sample pairs (2t, 2t+1) sharing weight LDS.
// =====================================================================
#define O_AW1 0
#define O_AB1 480
#define O_AW2 512
#define O_AB2 1536
#define O_AW3 1568
#define O_AB3 1696
#define O_PW1 1700
#define O_PB1 1892
#define O_PW2 1908
#define O_PB2 2164
#define O_PW3 2180
#define O_PB3 2436
#define O_DW1 2452
#define O_DW2 2692
#define O_DB2 2948
#define O_DW3 2964
#define O_DB3 3220
#define O_DW4 3236
#define O_DB4 3284
#define SW_TOT 3288

// paired layer: one weight LDS stream feeds two samples' accumulators
template<int IN, int OUTH>
__device__ __forceinline__ void layer2x2(const float* xA, const float* xB,
                                         const float* sw_w, const float* sw_b,
                                         u64* aA, u64* aB) {
    const u64* b2 = reinterpret_cast<const u64*>(sw_b);
#pragma unroll
    for (int j = 0; j < OUTH; j++) { aA[j] = b2[j]; aB[j] = b2[j]; }
#pragma unroll
    for (int i = 0; i < IN; i++) {
        u64 xa = pk2(xA[i], xA[i]);
        u64 xb = pk2(xB[i], xB[i]);
        const ulonglong2* w = reinterpret_cast<const ulonglong2*>(sw_w + i * (2*OUTH));
#pragma unroll
        for (int j = 0; j < OUTH/2; j++) {
            ulonglong2 ww = w[j];
            fma2(aA[2*j+0], xa, ww.x);
            fma2(aA[2*j+1], xa, ww.y);
            fma2(aB[2*j+0], xb, ww.x);
            fma2(aB[2*j+1], xb, ww.y);
        }
    }
}

template<int OUTH>
__device__ __forceinline__ void relu_unpack(const u64* acc, float* out) {
#pragma unroll
    for (int j = 0; j < OUTH; j++) {
        float a, b; upk2(acc[j], a, b);
        out[2*j]   = fmaxf(a, 0.f);
        out[2*j+1] = fmaxf(b, 0.f);
    }
}

__device__ __forceinline__ void trilerp(float px, float py, float pz, float* lat) {
    float gx = (px + 1.f) * 0.5f * 159.f;
    float gy = (py + 1.f) * 0.5f * 159.f;
    float gz = (pz + 1.f) * 0.5f * 159.f;
    float fx0 = floorf(gx), fy0 = floorf(gy), fz0 = floorf(gz);
    float wx1 = gx - fx0, wy1 = gy - fy0, wz1 = gz - fz0;
    float wx0 = 1.f - wx1, wy0 = 1.f - wy1, wz0 = 1.f - wz1;
    int ix0 = min(max((int)fx0, 0), 159); int ix1 = min(ix0 + 1, 159);
    int iy0 = min(max((int)fy0, 0), 159); int iy1 = min(iy0 + 1, 159);
    int iz0 = min(max((int)fz0, 0), 159); int iz1 = min(iz0 + 1, 159);

    u64 lat2[6];
#pragma unroll
    for (int k = 0; k < 6; k++) lat2[k] = 0ull;

#define ADD_CORNER(X, Y, Z, W) {                                                     \
        const ulonglong2* gp = reinterpret_cast<const ulonglong2*>(                  \
            g_grid_t + (size_t)((((X)*160 + (Y))*160) + (Z)) * 12);                  \
        ulonglong2 A = __ldg(gp), B = __ldg(gp+1), C = __ldg(gp+2);                  \
        float W_ = (W);                                                              \
        u64 wb = pk2(W_, W_);                                                        \
        fma2(lat2[0], wb, A.x); fma2(lat2[1], wb, A.y);                              \
        fma2(lat2[2], wb, B.x); fma2(lat2[3], wb, B.y);                              \
        fma2(lat2[4], wb, C.x); fma2(lat2[5], wb, C.y); }

    ADD_CORNER(ix0, iy0, iz0, wx0*wy0*wz0);
    ADD_CORNER(ix0, iy0, iz1, wx0*wy0*wz1);
    ADD_CORNER(ix0, iy1, iz0, wx0*wy1*wz0);
    ADD_CORNER(ix0, iy1, iz1, wx0*wy1*wz1);
    ADD_CORNER(ix1, iy0, iz0, wx1*wy0*wz0);
    ADD_CORNER(ix1, iy0, iz1, wx1*wy0*wz1);
    ADD_CORNER(ix1, iy1, iz0, wx1*wy1*wz0);
    ADD_CORNER(ix1, iy1, iz1, wx1*wy1*wz1);
#undef ADD_CORNER

#pragma unroll
    for (int k = 0; k < 6; k++) upk2(lat2[k], lat[2*k], lat[2*k+1]);
}

__global__ __launch_bounds__(288, 1) void k_main(
    const float* __restrict__ ro, const float* __restrict__ rd,
    const float* __restrict__ aw1, const float* __restrict__ ab1,
    const float* __restrict__ aw2, const float* __restrict__ ab2,
    const float* __restrict__ aw3, const float* __restrict__ ab3,
    const float* __restrict__ pw1, const float* __restrict__ pb1,
    const float* __restrict__ pw2, const float* __restrict__ pb2,
    const float* __restrict__ pw3, const float* __restrict__ pb3,
    const float* __restrict__ dw1,
    const float* __restrict__ dw2, const float* __restrict__ db2,
    const float* __restrict__ dw3, const float* __restrict__ db3,
    const float* __restrict__ dw4, const float* __restrict__ db4,
    float* __restrict__ out)
{
    __shared__ __align__(16) float sw[SW_TOT];
    __shared__ __align__(16) float s_db[16];
    __shared__ float s_ray[9];
    __shared__ __align__(16) float4 s_samp[NS];
    {
        int t = threadIdx.x;
        for (int i = t; i < 480;  i += 288) sw[O_AW1 + i] = aw1[i];
        for (int i = t; i < 32;   i += 288) sw[O_AB1 + i] = ab1[i];
        for (int i = t; i < 1024; i += 288) sw[O_AW2 + i] = aw2[i];
        for (int i = t; i < 32;   i += 288) sw[O_AB2 + i] = ab2[i];
        for (int i = t; i < 128;  i += 288) sw[O_AW3 + i] = aw3[i];
        for (int i = t; i < 4;    i += 288) sw[O_AB3 + i] = ab3[i];
        for (int i = t; i < 192;  i += 288) sw[O_PW1 + i] = pw1[i];
        for (int i = t; i < 16;   i += 288) sw[O_PB1 + i] = pb1[i];
        for (int i = t; i < 256;  i += 288) sw[O_PW2 + i] = pw2[i];
        for (int i = t; i < 16;   i += 288) sw[O_PB2 + i] = pb2[i];
        for (int i = t; i < 256;  i += 288) sw[O_PW3 + i] = pw3[i];
        for (int i = t; i < 16;   i += 288) sw[O_PB3 + i] = pb3[i];
        for (int i = t; i < 240;  i += 288) sw[O_DW1 + i] = dw1[i];  // rows 0..14
        for (int i = t; i < 256;  i += 288) sw[O_DW2 + i] = dw2[i];
        for (int i = t; i < 16;   i += 288) sw[O_DB2 + i] = db2[i];
        for (int i = t; i < 256;  i += 288) sw[O_DW3 + i] = dw3[i];
        for (int i = t; i < 16;   i += 288) sw[O_DB3 + i] = db3[i];
        for (int i = t; i < 48;   i += 288) sw[O_DW4 + i] = dw4[i];
        for (int i = t; i < 3;    i += 288) sw[O_DB4 + i] = db4[i];
        int ray0 = blockIdx.x;
        if (t < 16) s_db[t] = g_dbias[16*ray0 + t];
        if (t < 3)  s_ray[t] = g_rayinfo[4*ray0 + t];
        if (t >= 3 && t < 6) s_ray[t] = ro[3*ray0 + (t-3)];
        if (t >= 6 && t < 9) s_ray[t] = rd[3*ray0 + (t-6)];
    }
    __syncthreads();

    int t = threadIdx.x;
    float tmn = s_ray[0], rn = s_ray[1], mask = s_ray[2];
    float rinv = STEPW / rn;
    float ox = s_ray[3], oy = s_ray[4], oz = s_ray[5];
    float ddx = s_ray[6], ddy = s_ray[7], ddz = s_ray[8];

    if (t < NPAIR) {
        int s0 = 2*t, s1 = 2*t + 1;
        float itA = tmn + rinv * (float)s0;
        float itB = tmn + rinv * (float)s1;
        float pxA = ox + ddx*itA, pyA = oy + ddy*itA, pzA = oz + ddz*itA;
        float pxB = ox + ddx*itB, pyB = oy + ddy*itB, pzB = oz + ddz*itB;
        bool inbA = (mask == 0.f) && pxA >= -1.f && pxA <= 1.f &&
                    pyA >= -1.f && pyA <= 1.f && pzA >= -1.f && pzA <= 1.f;
        bool inbB = (mask == 0.f) && pxB >= -1.f && pxB <= 1.f &&
                    pyB >= -1.f && pyB <= 1.f && pzB >= -1.f && pzB <= 1.f;

        if (!inbA && !inbB) {
            s_samp[s0] = make_float4(0.f, 0.f, 0.f, 0.f);
            s_samp[s1] = make_float4(0.f, 0.f, 0.f, 0.f);
        } else {
            float latA[12], latB[12];
            trilerp(pxA, pyA, pzA, latA);
            trilerp(pxB, pyB, pzB, latB);

            // ---- attention MLP: 15 -> 32 -> 32 -> 4 -> softmax[1] ----
            float xinA[15], xinB[15];
            xinA[0] = pzA; xinA[1] = pyA; xinA[2] = pxA;
            xinB[0] = pzB; xinB[1] = pyB; xinB[2] = pxB;
#pragma unroll
            for (int k = 0; k < 12; k++) { xinA[3+k] = latA[k]; xinB[3+k] = latB[k]; }

            u64 aA16[16], aB16[16];
            float h1A[32], h1B[32], h2A[32], h2B[32];
            layer2x2<15, 16>(xinA, xinB, &sw[O_AW1], &sw[O_AB1], aA16, aB16);
            relu_unpack<16>(aA16, h1A); relu_unpack<16>(aB16, h1B);
            layer2x2<32, 16>(h1A, h1B, &sw[O_AW2], &sw[O_AB2], aA16, aB16);
            relu_unpack<16>(aA16, h2A); relu_unpack<16>(aB16, h2B);

            u64 oA[2], oB[2];
            layer2x2<32, 2>(h2A, h2B, &sw[O_AW3], &sw[O_AB3], oA, oB);
            float a0, a1, a2, a3, b0, b1, b2, b3;
            upk2(oA[0], a0, a1); upk2(oA[1], a2, a3);
            upk2(oB[0], b0, b1); upk2(oB[1], b2, b3);
            float mxA = fmaxf(fmaxf(a0, a1), fmaxf(a2, a3));
            float mxB = fmaxf(fmaxf(b0, b1), fmaxf(b2, b3));
            float attA = expf(a1-mxA) /
                (expf(a0-mxA) + expf(a1-mxA) + expf(a2-mxA) + expf(a3-mxA));
            float attB = expf(b1-mxB) /
                (expf(b0-mxB) + expf(b1-mxB) + expf(b2-mxB) + expf(b3-mxB));

            // ---- pos MLP: 12 -> 16 -> 16 -> 16 ----
            u64 pA8[8], pB8[8];
            float p1A[16], p1B[16], p2A[16], p2B[16], p3A[16], p3B[16];
            layer2x2<12, 8>(latA, latB, &sw[O_PW1], &sw[O_PB1], pA8, pB8);
            relu_unpack<8>(pA8, p1A); relu_unpack<8>(pB8, p1B);
            layer2x2<16, 8>(p1A, p1B, &sw[O_PW2], &sw[O_PB2], pA8, pB8);
            relu_unpack<8>(pA8, p2A); relu_unpack<8>(pB8, p2B);
            layer2x2<16, 8>(p2A, p2B, &sw[O_PW3], &sw[O_PB3], pA8, pB8);
#pragma unroll
            for (int j = 0; j < 8; j++) {
                upk2(pA8[j], p3A[2*j], p3A[2*j+1]);
                upk2(pB8[j], p3B[2*j], p3B[2*j+1]);
            }

            // ---- dir MLP: [p3[1:16]; emb-bias] -> 16 -> 16 -> 16 -> 3 ----
            float d1A[16], d1B[16], d2A[16], d2B[16], d3A[16], d3B[16];
            layer2x2<15, 8>(&p3A[1], &p3B[1], &sw[O_DW1], s_db, pA8, pB8);
            relu_unpack<8>(pA8, d1A); relu_unpack<8>(pB8, d1B);
            layer2x2<16, 8>(d1A, d1B, &sw[O_DW2], &sw[O_DB2], pA8, pB8);
            relu_unpack<8>(pA8, d2A); relu_unpack<8>(pB8, d2B);
            layer2x2<16, 8>(d2A, d2B, &sw[O_DW3], &sw[O_DB3], pA8, pB8);
            relu_unpack<8>(pA8, d3A); relu_unpack<8>(pB8, d3B);

            float rA0 = sw[O_DB4+0], rA1 = sw[O_DB4+1], rA2 = sw[O_DB4+2];
            float rB0 = rA0, rB1 = rA1, rB2 = rA2;
#pragma unroll
            for (int i = 0; i < 16; i++) {
                float w0 = sw[O_DW4 + i*3 + 0];
                float w1 = sw[O_DW4 + i*3 + 1];
                float w2 = sw[O_DW4 + i*3 + 2];
                rA0 += d3A[i]*w0; rA1 += d3A[i]*w1; rA2 += d3A[i]*w2;
                rB0 += d3B[i]*w0; rB1 += d3B[i]*w1; rB2 += d3B[i]*w2;
            }

            // ---- activations + store ----
            {
                float dens = attA * p3A[0];
                float xs = dens + ACT_SHIFT;
                float sp = fmaxf(xs, 0.f) + log1pf(expf(-fabsf(xs)));
                float alpha = 1.f - expf(-sp * 0.5f);
                float c0 = 1.f / (1.f + expf(-attA * rA0));
                float c1 = 1.f / (1.f + expf(-attA * rA1));
                float c2 = 1.f / (1.f + expf(-attA * rA2));
                s_samp[s0] = inbA ? make_float4(alpha, c0, c1, c2)
                                  : make_float4(0.f, 0.f, 0.f, 0.f);
            }
            {
                float dens = attB * p3B[0];
                float xs = dens + ACT_SHIFT;
                float sp = fmaxf(xs, 0.f) + log1pf(expf(-fabsf(xs)));
                float alpha = 1.f - expf(-sp * 0.5f);
                float c0 = 1.f / (1.f + expf(-attB * rB0));
                float c1 = 1.f / (1.f + expf(-attB * rB1));
                float c2 = 1.f / (1.f + expf(-attB * rB2));
                s_samp[s1] = inbB ? make_float4(alpha, c0, c1, c2)
                                  : make_float4(0.f, 0.f, 0.f, 0.f);
            }
        }
    }
    __syncthreads();

    // ---- per-ray compositing by warp 0 (shfl prefix-product scan) ----
    if (t < 32) {
        int lane = t;
        int ray = blockIdx.x;
        float base_depth = tmn * rn;
        float T = 1.f;
        float sr = 0.f, sg = 0.f, sb = 0.f, sd = 0.f, sa = 0.f;

        for (int c0 = 0; c0 < NS; c0 += 32) {
            int s = c0 + lane;
            float4 rec = (s < NS) ? s_samp[s] : make_float4(0.f, 0.f, 0.f, 0.f);
            float a = rec.x;
            float q = fmaxf(1.f - a, 1e-10f);
            float ip = q;
#pragma unroll
            for (int off = 1; off < 32; off <<= 1) {
                float v = __shfl_up_sync(0xFFFFFFFFu, ip, off);
                if (lane >= off) ip *= v;
            }
            float ep = __shfl_up_sync(0xFFFFFFFFu, ip, 1);
            if (lane == 0) ep = 1.f;
            float w = a * T * ep;
            sr += w * rec.y;
            sg += w * rec.z;
            sb += w * rec.w;
            sd += w * (base_depth + STEPW * (float)s);
            sa += w;
            T *= __shfl_sync(0xFFFFFFFFu, ip, 31);
        }

#pragma unroll
        for (int off = 16; off > 0; off >>= 1) {
            sr += __shfl_xor_sync(0xFFFFFFFFu, sr, off);
            sg += __shfl_xor_sync(0xFFFFFFFFu, sg, off);
            sb += __shfl_xor_sync(0xFFFFFFFFu, sb, off);
            sd += __shfl_xor_sync(0xFFFFFFFFu, sd, off);
            sa += __shfl_xor_sync(0xFFFFFFFFu, sa, off);
        }

        if (lane == 0) {
            float depth = sd + T * FARC;
            out[ray*6+0] = sr + T * BGC;
            out[ray*6+1] = sg + T * BGC;
            out[ray*6+2] = sb + T * BGC;
            out[ray*6+3] = depth;
            out[ray*6+4] = 1.f / depth;
            out[ray*6+5] = sa;
        }
    }
}

// =====================================================================
extern "C" void kernel_launch(void* const* d_in, const int* in_sizes, int n_in,
                              void* d_out, int out_size) {
    const float* ro  = (const float*)d_in[0];
    const float* rd  = (const float*)d_in[1];
    const float* vd  = (const float*)d_in[2];
    const float* grd = (const float*)d_in[3];
    const float* aw1 = (const float*)d_in[4];
    const float* ab1 = (const float*)d_in[5];
    const float* aw2 = (const float*)d_in[6];
    const float* ab2 = (const float*)d_in[7];
    const float* aw3 = (const float*)d_in[8];
    const float* ab3 = (const float*)d_in[9];
    const float* pw1 = (const float*)d_in[10];
    const float* pb1 = (const float*)d_in[11];
    const float* pw2 = (const float*)d_in[12];
    const float* pb2 = (const float*)d_in[13];
    const float* pw3 = (const float*)d_in[14];
    const float* pb3 = (const float*)d_in[15];
    const float* dw1 = (const float*)d_in[16];
    const float* db1 = (const float*)d_in[17];
    const float* dw2 = (const float*)d_in[18];
    const float* db2 = (const float*)d_in[19];
    const float* dw3 = (const float*)d_in[20];
    const float* db3 = (const float*)d_in[21];
    const float* dw4 = (const float*)d_in[22];
    const float* db4 = (const float*)d_in[23];

    k_transpose<<<(R3 + 255) / 256, 256>>>(grd);
    k_raypre<<<(NRAY + 255) / 256, 256>>>(ro, rd, vd, dw1, db1);
    k_main<<<NRAY, 288>>>(ro, rd,
                          aw1, ab1, aw2, ab2, aw3, ab3,
                          pw1, pb1, pw2, pb2, pw3, pb3,
                          dw1, dw2, db2, dw3, db3, dw4, db4,
                          (float*)d_out);
}